// round 14
// baseline (speedup 1.0000x reference)
#include <cuda_runtime.h>
#include <cuda_fp16.h>
#include <math.h>
#include <stdint.h>

// Problem constants
#define Bv   4
#define Sv   4096
#define Dv   1024
#define Hv   16
#define HDv  64
#define LKv  256
#define Mrows (Bv*Sv)                       // 16384
#define NELEM ((long long)Mrows * Dv)       // 16777216
#define PSPLIT 4                            // proj split-K ways

typedef __half h16;

// ---------------- scratch (static device globals; no allocation allowed) ----
__device__ h16 g_Xhi[NELEM];                    // X fp16 (A operand: hi only)
__device__ h16 g_Ehi[NELEM];                    // E fp16 (A operand: hi only)
__device__ h16 g_Wt_hi[4][(long long)Dv*Dv];    // weights transposed [n][k], hi
__device__ h16 g_Wt_lo[4][(long long)Dv*Dv];    // weights residual lo
__device__ h16 g_Kt_hi[NELEM], g_Kt_lo[NELEM];  // K^T [b][d][s], masked, hi/lo
__device__ h16 g_Vt_hi[NELEM], g_Vt_lo[NELEM];
__device__ h16 g_QHi[NELEM];                    // Q fp16 (A operand)
__device__ h16 g_XoHi[NELEM];                   // attn out fp16 (A operand)
__device__ h16 g_KpHi[(long long)Bv*Hv*LKv*HDv];    // Kp [bh][lk][64] hi/lo
__device__ h16 g_KpLo[(long long)Bv*Hv*LKv*HDv];
__device__ h16 g_VtpHi[(long long)Bv*Hv*HDv*LKv];   // Vp^T [bh][d][256] hi/lo
__device__ h16 g_VtpLo[(long long)Bv*Hv*HDv*LKv];
__device__ float g_PP[(long long)PSPLIT*Bv*Hv*2*128*128];  // proj partials
__device__ float g_bias3[3 * Dv];               // packed [bq|bk|bv]

// ---------------- helpers ----------------------------------------------------
__device__ __forceinline__ void hsplit(float v, h16& h, h16& l) {
    h = __float2half_rn(v);
    l = __float2half_rn(v - __half2float(h));
}
__device__ __forceinline__ unsigned pack2(h16 a, h16 b) {
    __half2 t = __halves2half2(a, b);
    return *reinterpret_cast<unsigned*>(&t);
}

// D += A(16x16,row) * B(16x8,col)   (fp16 in, fp32 acc)
__device__ __forceinline__ void mma_f16(float* d, const unsigned* a,
                                        const unsigned* b) {
    asm volatile(
        "mma.sync.aligned.m16n8k16.row.col.f32.f16.f16.f32 "
        "{%0,%1,%2,%3}, {%4,%5,%6,%7}, {%8,%9}, {%0,%1,%2,%3};\n"
        : "+f"(d[0]), "+f"(d[1]), "+f"(d[2]), "+f"(d[3])
        : "r"(a[0]), "r"(a[1]), "r"(a[2]), "r"(a[3]),
          "r"(b[0]), "r"(b[1]));
}

__device__ __forceinline__ void ldsm4(unsigned& r0, unsigned& r1,
                                      unsigned& r2, unsigned& r3, unsigned addr) {
    asm volatile("ldmatrix.sync.aligned.m8n8.x4.shared.b16 {%0,%1,%2,%3}, [%4];\n"
                 : "=r"(r0), "=r"(r1), "=r"(r2), "=r"(r3) : "r"(addr));
}

__device__ __forceinline__ void cp16(unsigned dst, const void* src) {
    asm volatile("cp.async.cg.shared.global [%0], [%1], 16;\n" :: "r"(dst), "l"(src));
}
__device__ __forceinline__ void cp_commit() { asm volatile("cp.async.commit_group;\n"); }
__device__ __forceinline__ void cp_wait1()  { asm volatile("cp.async.wait_group 1;\n"); }
__device__ __forceinline__ void cp_wait0()  { asm volatile("cp.async.wait_group 0;\n"); }

// swizzle for 64B rows: chunk' = chunk ^ ((row>>1)&3), in 16B units
__device__ __forceinline__ unsigned swz16(int row, int chunk) {
    return (unsigned)(row * 4 + (chunk ^ ((row >> 1) & 3)));
}

// ============================================================================
// GEMM core (fp16x2): C[128x128] += Ahi[128,*] * (Bhi+Blo)[128,*]^T
// 2 MMAs per output tile (hi*hi + hi*lo), issued hi-sweep then lo-sweep so
// same-accumulator MMAs are separated by 4 independent MMAs (RAW hiding).
// BK=32, 3-stage cp.async pipeline. Warps 2x4, warp tile 64x32.
// ============================================================================
template<int BSPLIT>
__device__ __forceinline__ void gemm_core(
    const h16* __restrict__ Ahg,
    const h16* __restrict__ Bhg, const h16* __restrict__ Blg,
    const h16* __restrict__ Bh2, const h16* __restrict__ Bl2,
    int K, int ld,
    float (&acc)[4][4][4])
{
    constexpr int BK = 32;
    constexpr int A_ELE = 128*BK, B_ELE = 128*BK;
    constexpr unsigned OF_BH = A_ELE*2;
    constexpr unsigned OF_BL = (A_ELE+B_ELE)*2;
    constexpr unsigned STAGE_B = (A_ELE+2*B_ELE)*2;   // 24576

    extern __shared__ h16 smem_dyn[];
    const unsigned s0 = (unsigned)__cvta_generic_to_shared(smem_dyn);

    const int t = threadIdx.x, lane = t & 31, warp = t >> 5;
    const int wm = warp >> 2, wn = warp & 3;
    const int m_w = wm * 64, n_w = wn * 32;

    // ---- cp.async mappings ----
    const int a_row = t >> 1;
    const int a_c0  = (t & 1) * 2;
    const unsigned a_d0 = swz16(a_row, a_c0)     * 16;
    const unsigned a_d1 = swz16(a_row, a_c0 + 1) * 16;

    const int b_row = t >> 1;
    const int b_c0  = (t & 1) * 2;
    const unsigned b_d0 = swz16(b_row, b_c0)     * 16;
    const unsigned b_d1 = swz16(b_row, b_c0 + 1) * 16;

    const h16* browH;
    const h16* browL;
    if (BSPLIT > 0 && b_row >= BSPLIT) {
        browH = Bh2 + (size_t)(b_row - BSPLIT) * ld;
        browL = Bl2 + (size_t)(b_row - BSPLIT) * ld;
    } else {
        browH = Bhg + (size_t)b_row * ld;
        browL = Blg + (size_t)b_row * ld;
    }

    auto issue = [&](int st, int k0) {
        const unsigned sbs = s0 + (unsigned)st * STAGE_B;
        const char* pah = (const char*)(Ahg + (size_t)a_row * ld + k0);
        cp16(sbs + a_d0, pah + a_c0*16);
        cp16(sbs + a_d1, pah + a_c0*16 + 16);
        const char* pbh = (const char*)(browH + k0);
        const char* pbl = (const char*)(browL + k0);
        cp16(sbs + OF_BH + b_d0, pbh + b_c0*16);
        cp16(sbs + OF_BH + b_d1, pbh + b_c0*16 + 16);
        cp16(sbs + OF_BL + b_d0, pbl + b_c0*16);
        cp16(sbs + OF_BL + b_d1, pbl + b_c0*16 + 16);
    };

    // ---- ldmatrix fragment addresses ----
    const int lr  = lane & 7;
    const int aLR = lr + ((lane >> 3) & 1) * 8;
    const int aLC = lane >> 4;
    unsigned adA[4][2];
    #pragma unroll
    for (int mt = 0; mt < 4; mt++)
        #pragma unroll
        for (int ks = 0; ks < 2; ks++) {
            int row = m_w + mt*16 + aLR;
            adA[mt][ks] = swz16(row, 2*ks + aLC) * 16;
        }
    const int j   = lane >> 3;
    const int bLR = ((j >> 1) & 1) * 8 + lr;
    const int bLC = j & 1;
    unsigned adB[2][2];
    #pragma unroll
    for (int p = 0; p < 2; p++)
        #pragma unroll
        for (int ks = 0; ks < 2; ks++) {
            int row = n_w + p*16 + bLR;
            adB[p][ks] = swz16(row, 2*ks + bLC) * 16;
        }

    const int ntiles = K / BK;
    issue(0, 0); cp_commit();
    if (ntiles > 1) { issue(1, BK); cp_commit(); }

    for (int i = 0; i < ntiles; i++) {
        if (i + 1 < ntiles) cp_wait1(); else cp_wait0();
        __syncthreads();
        if (i + 2 < ntiles) { issue((i + 2) % 3, (i + 2) * BK); cp_commit(); }

        const unsigned sbs = s0 + (unsigned)(i % 3) * STAGE_B;
        #pragma unroll
        for (int ks = 0; ks < 2; ks++) {
            unsigned bh[4][2], bl[4][2];
            #pragma unroll
            for (int p = 0; p < 2; p++) {
                ldsm4(bh[2*p][0], bh[2*p][1], bh[2*p+1][0], bh[2*p+1][1],
                      sbs + OF_BH + adB[p][ks]);
                ldsm4(bl[2*p][0], bl[2*p][1], bl[2*p+1][0], bl[2*p+1][1],
                      sbs + OF_BL + adB[p][ks]);
            }
            #pragma unroll
            for (int mt = 0; mt < 4; mt++) {
                unsigned ah[4];
                ldsm4(ah[0], ah[1], ah[2], ah[3], sbs + adA[mt][ks]);
                // hi sweep (4 independent accumulators), then lo sweep:
                // same-acc RAW pairs are 4 MMAs apart.
                #pragma unroll
                for (int nt = 0; nt < 4; nt++)
                    mma_f16(acc[mt][nt], ah, bh[nt]);
                #pragma unroll
                for (int nt = 0; nt < 4; nt++)
                    mma_f16(acc[mt][nt], ah, bl[nt]);
            }
        }
    }
}

// ============================================================================
// Fused QKV GEMM (CTA 128x128). grid = (24, 128).
// ============================================================================
__global__ __launch_bounds__(256) void gemm_qkv(
    const h16* __restrict__ Ahi,
    const h16* __restrict__ Bhi, const h16* __restrict__ Blo,
    const float* __restrict__ mask)
{
    extern __shared__ h16 smem_dyn[];
    const int m0 = blockIdx.y * 128, n0 = blockIdx.x * 128;
    float acc[4][4][4];
    #pragma unroll
    for (int a = 0; a < 4; a++)
        #pragma unroll
        for (int b = 0; b < 4; b++)
            #pragma unroll
            for (int c = 0; c < 4; c++) acc[a][b][c] = 0.0f;

    gemm_core<0>(Ahi + (size_t)m0 * Dv,
                 Bhi + (size_t)n0 * Dv, Blo + (size_t)n0 * Dv,
                 nullptr, nullptr, Dv, Dv, acc);

    const int t = threadIdx.x;
    const int lane = t & 31, warp = t >> 5;
    const int wm = warp >> 2, wn = warp & 3;
    const int gid = lane >> 2, tig = lane & 3;

    const bool isQ = (n0 < Dv);
    const bool isV = (n0 >= 2 * Dv);
    const int dbase = isQ ? 0 : (isV ? 2 * Dv : Dv);

    if (isQ) {
        #pragma unroll
        for (int mt = 0; mt < 4; mt++) {
            const int r0 = m0 + wm * 64 + mt * 16 + gid;
            #pragma unroll
            for (int nt = 0; nt < 4; nt++) {
                const int c = n0 + wn * 32 + nt * 8 + tig * 2;
                const float b0 = g_bias3[c], b1 = g_bias3[c + 1];
                *(unsigned*)&g_QHi[(size_t)r0 * Dv + c] =
                    pack2(__float2half_rn(acc[mt][nt][0] + b0),
                          __float2half_rn(acc[mt][nt][1] + b1));
                *(unsigned*)&g_QHi[(size_t)(r0+8) * Dv + c] =
                    pack2(__float2half_rn(acc[mt][nt][2] + b0),
                          __float2half_rn(acc[mt][nt][3] + b1));
            }
        }
    } else {
        h16* oh = isV ? g_Vt_hi : g_Kt_hi;
        h16* ol = isV ? g_Vt_lo : g_Kt_lo;
        float* Ts = (float*)smem_dyn;
        __syncthreads();
        #pragma unroll
        for (int mt = 0; mt < 4; mt++) {
            const int ml = wm * 64 + mt * 16 + gid;
            const int r0 = m0 + ml;
            const float ms0 = mask[r0], ms1 = mask[r0 + 8];
            #pragma unroll
            for (int nt = 0; nt < 4; nt++) {
                const int nl = wn * 32 + nt * 8 + tig * 2;
                const int c  = n0 + nl;
                const float b0 = g_bias3[c], b1 = g_bias3[c + 1];
                Ts[nl*132 + ml]         = (acc[mt][nt][0] + b0) * ms0;
                Ts[(nl+1)*132 + ml]     = (acc[mt][nt][1] + b1) * ms0;
                Ts[nl*132 + ml + 8]     = (acc[mt][nt][2] + b0) * ms1;
                Ts[(nl+1)*132 + ml + 8] = (acc[mt][nt][3] + b1) * ms1;
            }
        }
        __syncthreads();
        const int nl = t >> 1, mc = (t & 1) * 64;
        const int d  = n0 - dbase + nl;
        const size_t ad = ((size_t)(m0 >> 12) << 22) + (size_t)d * 4096
                        + (m0 & 4095) + mc;
        unsigned hb[32], lb[32];
        #pragma unroll
        for (int i = 0; i < 32; i++) {
            float2 v = *(float2*)&Ts[nl*132 + mc + 2*i];
            h16 h0,l0,h1,l1; hsplit(v.x,h0,l0); hsplit(v.y,h1,l1);
            hb[i] = pack2(h0,h1); lb[i] = pack2(l0,l1);
        }
        #pragma unroll
        for (int i = 0; i < 8; i++) {
            *(uint4*)&oh[ad + i*8] = ((uint4*)hb)[i];
            *(uint4*)&ol[ad + i*8] = ((uint4*)lb)[i];
        }
    }
}

// ============================================================================
// Output GEMM: out = Xo @ Wo + bo (fp32). grid = (8, 128).
// ============================================================================
__global__ __launch_bounds__(256) void gemm_out(
    const h16* __restrict__ Ahi,
    const h16* __restrict__ Bhi, const h16* __restrict__ Blo,
    const float* __restrict__ bias, float* __restrict__ outf)
{
    const int m0 = blockIdx.y * 128, n0 = blockIdx.x * 128;
    float acc[4][4][4];
    #pragma unroll
    for (int a = 0; a < 4; a++)
        #pragma unroll
        for (int b = 0; b < 4; b++)
            #pragma unroll
            for (int c = 0; c < 4; c++) acc[a][b][c] = 0.0f;

    gemm_core<0>(Ahi + (size_t)m0 * Dv,
                 Bhi + (size_t)n0 * Dv, Blo + (size_t)n0 * Dv,
                 nullptr, nullptr, Dv, Dv, acc);

    const int lane = threadIdx.x & 31, warp = threadIdx.x >> 5;
    const int wm = warp >> 2, wn = warp & 3;
    const int gid = lane >> 2, tig = lane & 3;

    #pragma unroll
    for (int mt = 0; mt < 4; mt++) {
        const int r0 = m0 + wm * 64 + mt * 16 + gid;
        #pragma unroll
        for (int nt = 0; nt < 4; nt++) {
            const int c = n0 + wn * 32 + nt * 8 + tig * 2;
            const float b0 = bias[c], b1 = bias[c + 1];
            *(float2*)&outf[(size_t)r0       * Dv + c] =
                make_float2(acc[mt][nt][0] + b0, acc[mt][nt][1] + b1);
            *(float2*)&outf[(size_t)(r0 + 8) * Dv + c] =
                make_float2(acc[mt][nt][2] + b0, acc[mt][nt][3] + b1);
        }
    }
}

// ============================================================================
// Projection split-K stage 1: partial over s-slice. grid = (2, 64, PSPLIT).
// ============================================================================
__global__ __launch_bounds__(256) void proj_part()
{
    const int m0 = blockIdx.x * 128;
    const int bh = blockIdx.y;
    const int z  = blockIdx.z;
    const int b  = bh >> 4, h = bh & 15;
    const int soff = z * (Sv / PSPLIT);

    const h16* Ah = g_Ehi + ((size_t)h * LKv + m0) * Sv + soff;
    const size_t boff = (size_t)(b * Dv + h * HDv) * Sv + soff;

    float acc[4][4][4];
    #pragma unroll
    for (int a = 0; a < 4; a++)
        #pragma unroll
        for (int c = 0; c < 4; c++)
            #pragma unroll
            for (int r = 0; r < 4; r++) acc[a][c][r] = 0.0f;

    gemm_core<64>(Ah,
                  g_Kt_hi + boff, g_Kt_lo + boff,
                  g_Vt_hi + boff, g_Vt_lo + boff,
                  Sv / PSPLIT, Sv, acc);

    const int lane = threadIdx.x & 31, warp = threadIdx.x >> 5;
    const int wm = warp >> 2, wn = warp & 3;
    const int gid = lane >> 2, tig = lane & 3;

    float* pp = g_PP + (((size_t)z * (Bv*Hv) + bh) * 2 + blockIdx.x) * 128 * 128;
    #pragma unroll
    for (int mt = 0; mt < 4; mt++) {
        const int ml = wm * 64 + mt * 16 + gid;
        #pragma unroll
        for (int nt = 0; nt < 4; nt++) {
            const int nl = wn * 32 + nt * 8 + tig * 2;
            *(float2*)&pp[(size_t)ml * 128 + nl]       =
                make_float2(acc[mt][nt][0], acc[mt][nt][1]);
            *(float2*)&pp[(size_t)(ml + 8) * 128 + nl] =
                make_float2(acc[mt][nt][2], acc[mt][nt][3]);
        }
    }
}

// ============================================================================
// Projection split-K stage 2: sum partials, split-store Kp + VpT (coalesced).
// grid = (2, 64), 256 threads, smem Ts[128][132] fp32.
// ============================================================================
__global__ __launch_bounds__(256) void proj_reduce()
{
    extern __shared__ h16 smem_dyn[];
    float* Ts = (float*)smem_dyn;
    const int m0 = blockIdx.x * 128;
    const int bh = blockIdx.y;
    const int t  = threadIdx.x;

    const float* pp = g_PP + ((size_t)bh * 2 + blockIdx.x) * 128 * 128;
    const size_t zstride = (size_t)(Bv*Hv) * 2 * 128 * 128;

    #pragma unroll
    for (int i = 0; i < 16; i++) {
        int idx = t + i * 256;
        int ml = idx >> 5, nc = idx & 31;
        float4 s = *(const float4*)&pp[(size_t)ml * 128 + nc * 4];
        #pragma unroll
        for (int z = 1; z < PSPLIT; z++) {
            float4 v = *(const float4*)&pp[z * zstride + (size_t)ml * 128 + nc * 4];
            s.x += v.x; s.y += v.y; s.z += v.z; s.w += v.w;
        }
        *(float4*)&Ts[ml * 132 + nc * 4] = s;
    }
    __syncthreads();

    h16* kpH = g_KpHi + (size_t)bh * LKv * HDv;
    h16* kpL = g_KpLo + (size_t)bh * LKv * HDv;
    h16* vtH = g_VtpHi + (size_t)bh * HDv * LKv;
    h16* vtL = g_VtpLo + (size_t)bh * HDv * LKv;

    // Kp: [lk][64] coalesced
    {
        const int lk = t >> 1, c0 = (t & 1) * 32;
        unsigned hb[16], lb[16];
        #pragma unroll
        for (int i = 0; i < 16; i++) {
            float2 v = *(float2*)&Ts[lk*132 + c0 + 2*i];
            h16 h0,l0,h1,l1; hsplit(v.x,h0,l0); hsplit(v.y,h1,l1);
            hb[i] = pack2(h0,h1); lb[i] = pack2(l0,l1);
        }
        const size_t base = (size_t)(m0 + lk) * HDv + c0;
        #pragma unroll
        for (int i = 0; i < 4; i++) {
            *(uint4*)&kpH[base + i*8] = ((uint4*)hb)[i];
            *(uint4*)&kpL[base + i*8] = ((uint4*)lb)[i];
        }
    }
    // VpT: [d][256] coalesced
    {
        const int d = t >> 2, kc = (t & 3) * 32;
        unsigned hb[16], lb[16];
        #pragma unroll
        for (int i = 0; i < 16; i++) {
            float va = Ts[(kc + 2*i)*132 + 64 + d];
            float vb = Ts[(kc + 2*i + 1)*132 + 64 + d];
            h16 h0,l0,h1,l1; hsplit(va,h0,l0); hsplit(vb,h1,l1);
            hb[i] = pack2(h0,h1); lb[i] = pack2(l0,l1);
        }
        const size_t base = (size_t)d * LKv + m0 + kc;
        #pragma unroll
        for (int i = 0; i < 4; i++) {
            *(uint4*)&vtH[base + i*8] = ((uint4*)hb)[i];
            *(uint4*)&vtL[base + i*8] = ((uint4*)lb)[i];
        }
    }
}

// ============================================================================
// Prepass kernels
// ============================================================================
#define NB_SPLIT ((int)(NELEM/4/256))   // 16384

__global__ void prepass_split(const float* __restrict__ X, const float* __restrict__ E,
                              const float* __restrict__ bq, const float* __restrict__ bk,
                              const float* __restrict__ bv)
{
    const int bid = blockIdx.x;
    if (bid < 2 * NB_SPLIT) {
        const bool isX = bid < NB_SPLIT;
        const float* in = isX ? X : E;
        h16* hi = isX ? g_Xhi : g_Ehi;
        const int base = (isX ? bid : bid - NB_SPLIT);
        long long i = ((long long)base * 256 + threadIdx.x);
        float4 v = *(const float4*)&in[i * 4];
        uint2 o;
        o.x = pack2(__float2half_rn(v.x), __float2half_rn(v.y));
        o.y = pack2(__float2half_rn(v.z), __float2half_rn(v.w));
        *(uint2*)&hi[i * 4] = o;
    } else {
        for (int i = threadIdx.x; i < 3 * Dv; i += 256) {
            g_bias3[i] = (i < Dv) ? bq[i]
                       : (i < 2 * Dv) ? bk[i - Dv] : bv[i - 2 * Dv];
        }
    }
}

__global__ void prepass_tsplit(const float* __restrict__ Wq, const float* __restrict__ Wk,
                               const float* __restrict__ Wv, const float* __restrict__ Wo)
{
    __shared__ float ts[32][33];
    const float* in = (blockIdx.z == 0) ? Wq : (blockIdx.z == 1) ? Wk
                    : (blockIdx.z == 2) ? Wv : Wo;
    h16* hi = g_Wt_hi[blockIdx.z];
    h16* lo = g_Wt_lo[blockIdx.z];
    const int bx = blockIdx.x * 32, by = blockIdx.y * 32;
    const int tx = threadIdx.x, ty = threadIdx.y;
    #pragma unroll
    for (int j = 0; j < 4; j++)
        ts[ty + j * 8][tx] = in[(size_t)(by + ty + j * 8) * Dv + bx + tx];
    __syncthreads();
    #pragma unroll
    for (int j = 0; j < 4; j++) {
        float v = ts[tx][ty + j * 8];
        h16 h, l; hsplit(v, h, l);
        size_t ad = (size_t)(bx + ty + j * 8) * Dv + by + tx;
        hi[ad] = h; lo[ad] = l;
    }
}

// ============================================================================
// Tensorized attention, online softmax, fp16x2 with RAW-spread MMA ordering.
// smem: QH 0 (16K) | KH 16K | KL 32K | VH 48K | VL 64K  (80KB)
// ============================================================================
#define ATTN_SMEM 81920

__global__ __launch_bounds__(256) void attn_mma()
{
    extern __shared__ char smraw[];
    const unsigned sb = (unsigned)__cvta_generic_to_shared(smraw);

    const int t = threadIdx.x, lane = t & 31, warp = t >> 5;
    const int bh = blockIdx.y, b = bh >> 4, h = bh & 15;
    const int q0 = blockIdx.x * 128;

    const h16* QgH = g_QHi + (size_t)(b * Sv + q0) * Dv + h * HDv;
    const h16* KpH = g_KpHi + (size_t)bh * LKv * HDv;
    const h16* KpL = g_KpLo + (size_t)bh * LKv * HDv;
    const h16* VtH = g_VtpHi + (size_t)bh * HDv * LKv;
    const h16* VtL = g_VtpLo + (size_t)bh * HDv * LKv;

    const unsigned QH = 0, KH = 16384, KL = 32768, VH = 49152, VL = 65536;

    const int qrow = t >> 1, qc0 = (t & 1) * 4;
    const int vrow = t >> 2, vc0 = (t & 3) * 4;

    #pragma unroll
    for (int c4 = 0; c4 < 4; c4++) {
        int ch = qc0 + c4;
        unsigned off = (unsigned)qrow * 128 + (unsigned)(ch ^ (qrow & 7)) * 16;
        cp16(sb + QH + off, QgH + (size_t)qrow * Dv + ch * 8);
    }

    auto stageKV = [&](int c) {
        #pragma unroll
        for (int c4 = 0; c4 < 4; c4++) {
            int ch = qc0 + c4;
            unsigned off = (unsigned)qrow * 128 + (unsigned)(ch ^ (qrow & 7)) * 16;
            cp16(sb + KH + off, KpH + (size_t)(c * 128 + qrow) * HDv + ch * 8);
            cp16(sb + KL + off, KpL + (size_t)(c * 128 + qrow) * HDv + ch * 8);
        }
        #pragma unroll
        for (int c4 = 0; c4 < 4; c4++) {
            int ch = vc0 + c4;
            unsigned off = (unsigned)vrow * 256 + (unsigned)(ch ^ (vrow & 7)) * 16;
            cp16(sb + VH + off, VtH + (size_t)vrow * LKv + c * 128 + ch * 8);
            cp16(sb + VL + off, VtL + (size_t)vrow * LKv + c * 128 + ch * 8);
        }
    };

    stageKV(0);
    cp_commit();

    const int gid = lane >> 2, tig = lane & 3;
    const int lr  = lane & 7;
    const int aLR = lr + ((lane >> 3) & 1) * 8;
    const int aLC = lane >> 4;
    const int jj  = lane >> 3;
    const int bLR = ((jj >> 1) & 1) * 8 + lr;
    const int bLC = jj & 1;
    const int m_w = warp * 16;
    const int rowA = m_w + aLR;

    float avacc[8][4];
    #pragma unroll
    for (int nt = 0; nt < 8; nt++)
        #pragma unroll
        for (int r = 0; r < 4; r++) avacc[nt][r] = 0.0f;
    float m0r = -1e30f, m1r = -1e30f, sum0 = 0.0f, sum1 = 0.0f;

    for (int c = 0; c < 2; c++) {
        cp_wait0();
        __syncthreads();

        // ---- scores S[16 x 128] = Q . Kp^T (pairs of p, hi sweep then lo) ----
        float sacc[16][4];
        #pragma unroll
        for (int nt = 0; nt < 16; nt++)
            #pragma unroll
            for (int r = 0; r < 4; r++) sacc[nt][r] = 0.0f;

        #pragma unroll
        for (int ks = 0; ks < 4; ks++) {
            unsigned qh[4];
            unsigned aoff = (unsigned)rowA * 128 + ((unsigned)((2*ks + aLC) ^ (rowA & 7))) * 16;
            ldsm4(qh[0], qh[1], qh[2], qh[3], sb + QH + aoff);
            #pragma unroll
            for (int p = 0; p < 8; p += 2) {
                int rB0 = p * 16 + bLR, rB1 = (p + 1) * 16 + bLR;
                unsigned bo0 = (unsigned)rB0 * 128 + ((unsigned)((2*ks + bLC) ^ (rB0 & 7))) * 16;
                unsigned bo1 = (unsigned)rB1 * 128 + ((unsigned)((2*ks + bLC) ^ (rB1 & 7))) * 16;
                unsigned kh0[4], kl0[4], kh1[4], kl1[4];
                ldsm4(kh0[0], kh0[1], kh0[2], kh0[3], sb + KH + bo0);
                ldsm4(kl0[0], kl0[1], kl0[2], kl0[3], sb + KL + bo0);
                ldsm4(kh1[0], kh1[1], kh1[2], kh1[3], sb + KH + bo1);
                ldsm4(kl1[0], kl1[1], kl1[2], kl1[3], sb + KL + bo1);
                // hi sweep over 4 accumulators, then lo sweep (RAW sep = 3)
                mma_f16(sacc[2*p],   qh, &kh0[0]);
                mma_f16(sacc[2*p+1], qh, &kh0[2]);
                mma_f16(sacc[2*p+2], qh, &kh1[0]);
                mma_f16(sacc[2*p+3], qh, &kh1[2]);
                mma_f16(sacc[2*p],   qh, &kl0[0]);
                mma_f16(sacc[2*p+1], qh, &kl0[2]);
                mma_f16(sacc[2*p+2], qh, &kl1[0]);
                mma_f16(sacc[2*p+3], qh, &kl1[2]);
            }
        }

        // ---- online softmax update ----
        float mc0 = -1e30f, mc1 = -1e30f;
        #pragma unroll
        for (int nt = 0; nt < 16; nt++) {
            mc0 = fmaxf(mc0, fmaxf(sacc[nt][0], sacc[nt][1]));
            mc1 = fmaxf(mc1, fmaxf(sacc[nt][2], sacc[nt][3]));
        }
        mc0 *= 0.125f; mc1 *= 0.125f;
        mc0 = fmaxf(mc0, __shfl_xor_sync(0xffffffffu, mc0, 1));
        mc0 = fmaxf(mc0, __shfl_xor_sync(0xffffffffu, mc0, 2));
        mc1 = fmaxf(mc1, __shfl_xor_sync(0xffffffffu, mc1, 1));
        mc1 = fmaxf(mc1, __shfl_xor_sync(0xffffffffu, mc1, 2));
        const float mn0 = fmaxf(m0r, mc0), mn1 = fmaxf(m1r, mc1);
        const float sc0 = __expf(m0r - mn0), sc1 = __expf(m1r - mn1);
        m0r = mn0; m1r = mn1;

        float rs0 = 0.0f, rs1 = 0.0f;
        #pragma unroll
        for (int nt = 0; nt < 16; nt++) {
            float p0 = __expf(0.125f * sacc[nt][0] - mn0);
            float p1 = __expf(0.125f * sacc[nt][1] - mn0);
            float p2 = __expf(0.125f * sacc[nt][2] - mn1);
            float p3 = __expf(0.125f * sacc[nt][3] - mn1);
            sacc[nt][0] = p0; sacc[nt][1] = p1; sacc[nt][2] = p2; sacc[nt][3] = p3;
            rs0 += p0 + p1; rs1 += p2 + p3;
        }
        rs0 += __shfl_xor_sync(0xffffffffu, rs0, 1);
        rs0 += __shfl_xor_sync(0xffffffffu, rs0, 2);
        rs1 += __shfl_xor_sync(0xffffffffu, rs1, 1);
        rs1 += __shfl_xor_sync(0xffffffffu, rs1, 2);
        sum0 = sum0 * sc0 + rs0;
        sum1 = sum1 * sc1 + rs1;
        #pragma unroll
        for (int nt = 0; nt < 8; nt++) {
            avacc[nt][0] *= sc0; avacc[nt][1] *= sc0;
            avacc[nt][2] *= sc1; avacc[nt][3] *= sc1;
        }

        // ---- AV: Xo += P . VpT^T (pairs of p, hi sweep then lo) ----
        #pragma unroll
        for (int kt = 0; kt < 8; kt++) {
            unsigned ah[4] = {
                pack2(__float2half_rn(sacc[2*kt][0]),   __float2half_rn(sacc[2*kt][1])),
                pack2(__float2half_rn(sacc[2*kt][2]),   __float2half_rn(sacc[2*kt][3])),
                pack2(__float2half_rn(sacc[2*kt+1][0]), __float2half_rn(sacc[2*kt+1][1])),
                pack2(__float2half_rn(sacc[2*kt+1][2]), __float2half_rn(sacc[2*kt+1][3]))
            };
            #pragma unroll
            for (int p = 0; p < 4; p += 2) {
                int rB0 = p * 16 + bLR, rB1 = (p + 1) * 16 + bLR;
                unsigned bo0 = (unsigned)rB0 * 256 + ((unsigned)((2*kt + bLC) ^ (rB0 & 7))) * 16;
                unsigned bo1 = (unsigned)rB1 * 256 + ((unsigned)((2*kt + bLC) ^ (rB1 & 7))) * 16;
                unsigned vh0[4], vl0[4], vh1[4], vl1[4];
                ldsm4(vh0[0], vh0[1], vh0[2], vh0[3], sb + VH + bo0);
                ldsm4(vl0[0], vl0[1], vl0[2], vl0[3], sb + VL + bo0);
                ldsm4(vh1[0], vh1[1], vh1[2], vh1[3], sb + VH + bo1);
                ldsm4(vl1[0], vl1[1], vl1[2], vl1[3], sb + VL + bo1);
                mma_f16(avacc[2*p],   ah, &vh0[0]);
                mma_f16(avacc[2*p+1], ah, &vh0[2]);
                mma_f16(avacc[2*p+2], ah, &vh1[0]);
                mma_f16(avacc[2*p+3], ah, &vh1[2]);
                mma_f16(avacc[2*p],   ah, &vl0[0]);
                mma_f16(avacc[2*p+1], ah, &vl0[2]);
                mma_f16(avacc[2*p+2], ah, &vl1[0]);
                mma_f16(avacc[2*p+3], ah, &vl1[2]);
            }
        }
        __syncthreads();
        if (c == 0) { stageKV(1); cp_commit(); }
    }

    // ---- finalize: divide by sum, stage, fp16 store ----
    const float i0 = 1.0f / sum0, i1 = 1.0f / sum1;
    float* Xs = (float*)(smraw + 16384);
    #pragma unroll
    for (int nt = 0; nt < 8; nt++) {
        const int col = 8 * nt + 2 * tig;
        Xs[(m_w + gid)     * 64 + col]     = avacc[nt][0] * i0;
        Xs[(m_w + gid)     * 64 + col + 1] = avacc[nt][1] * i0;
        Xs[(m_w + gid + 8) * 64 + col]     = avacc[nt][2] * i1;
        Xs[(m_w + gid + 8) * 64 + col + 1] = avacc[nt][3] * i1;
    }
    __syncthreads();

    #pragma unroll
    for (int r = 0; r < 8; r++) {
        int i = (t + r * 256) * 4;
        int row = i >> 6, d0 = i & 63;
        float4 v = *(const float4*)&Xs[row * 64 + d0];
        size_t ad = ((size_t)(b * Sv + q0 + row)) * Dv + h * HDv + d0;
        uint2 o;
        o.x = pack2(__float2half_rn(v.x), __float2half_rn(v.y));
        o.y = pack2(__float2half_rn(v.z), __float2half_rn(v.w));
        *(uint2*)&g_XoHi[ad] = o;
    }
}

// ============================================================================
extern "C" void kernel_launch(void* const* d_in, const int* in_sizes, int n_in,
                              void* d_out, int out_size)
{
    const float* X    = (const float*)d_in[0];
    const float* mask = (const float*)d_in[1];
    const float* Wq   = (const float*)d_in[2];
    const float* bq   = (const float*)d_in[3];
    const float* Wk   = (const float*)d_in[4];
    const float* bk   = (const float*)d_in[5];
    const float* Wv   = (const float*)d_in[6];
    const float* bv   = (const float*)d_in[7];
    const float* E    = (const float*)d_in[8];
    const float* Wo   = (const float*)d_in[9];
    const float* bo   = (const float*)d_in[10];
    float* out        = (float*)d_out;

    h16 *xhi, *wth, *wtl, *xoh;
    cudaGetSymbolAddress((void**)&xhi, g_Xhi);
    cudaGetSymbolAddress((void**)&wth, g_Wt_hi);
    cudaGetSymbolAddress((void**)&wtl, g_Wt_lo);
    cudaGetSymbolAddress((void**)&xoh, g_XoHi);

    const long long WSZ = (long long)Dv * Dv;

    const int SMEM_G = 3 * 24576;       // fp16x2 core: 3 stages x 24KB
    const int SMEM_R = 128 * 132 * 4;   // reduce staging
    cudaFuncSetAttribute(gemm_qkv,   cudaFuncAttributeMaxDynamicSharedMemorySize, SMEM_G);
    cudaFuncSetAttribute(gemm_out,   cudaFuncAttributeMaxDynamicSharedMemorySize, SMEM_G);
    cudaFuncSetAttribute(proj_part,  cudaFuncAttributeMaxDynamicSharedMemorySize, SMEM_G);
    cudaFuncSetAttribute(proj_reduce,cudaFuncAttributeMaxDynamicSharedMemorySize, SMEM_R);
    cudaFuncSetAttribute(attn_mma,   cudaFuncAttributeMaxDynamicSharedMemorySize, ATTN_SMEM);

    // launch 1: convert X + E to fp16, pack bias
    prepass_split<<<2 * NB_SPLIT + 1, 256>>>(X, E, bq, bk, bv);
    // launch 2: transpose+split all weights (fp16 hi/lo)
    prepass_tsplit<<<dim3(32, 32, 4), dim3(32, 8)>>>(Wq, Wk, Wv, Wo);
    // launch 3: fused QKV
    gemm_qkv<<<dim3(3 * Dv / 128, Mrows / 128), 256, SMEM_G>>>(xhi, wth, wtl, mask);
    // launch 4: proj partials (split-K)
    proj_part<<<dim3(LKv / 128, Bv * Hv, PSPLIT), 256, SMEM_G>>>();
    // launch 5: proj reduce + split stores
    proj_reduce<<<dim3(LKv / 128, Bv * Hv), 256, SMEM_R>>>();
    // launch 6: attention
    attn_mma<<<dim3(Sv / 128, Bv * Hv), 256, ATTN_SMEM>>>();
    // launch 7: output projection
    gemm_out<<<dim3(Dv / 128, Mrows / 128), 256, SMEM_G>>>(xoh, wth + 3*WSZ, wtl + 3*WSZ,
                                                           bo, out);
}

// round 17
// speedup vs baseline: 1.0404x; 1.0404x over previous
#include <cuda_runtime.h>
#include <cuda_fp16.h>
#include <math.h>
#include <stdint.h>

// Problem constants
#define Bv   4
#define Sv   4096
#define Dv   1024
#define Hv   16
#define HDv  64
#define LKv  256
#define Mrows (Bv*Sv)                       // 16384
#define NELEM ((long long)Mrows * Dv)       // 16777216
#define PSPLIT 4                            // proj split-K ways

typedef __half h16;

// ---------------- scratch (static device globals; no allocation allowed) ----
__device__ h16 g_Xhi[NELEM];                    // X fp16 (A operand: hi only)
__device__ h16 g_Ehi[NELEM];                    // E fp16 (A operand: hi only)
__device__ h16 g_Wt_hi[4][(long long)Dv*Dv];    // weights transposed [n][k], hi
__device__ h16 g_Wt_lo[4][(long long)Dv*Dv];    // weights residual lo
__device__ h16 g_Kt_hi[NELEM], g_Kt_lo[NELEM];  // K^T [b][d][s], masked, hi/lo
__device__ h16 g_Vt_hi[NELEM], g_Vt_lo[NELEM];
__device__ h16 g_QHi[NELEM];                    // Q fp16 (A operand)
__device__ h16 g_XoHi[NELEM];                   // attn out fp16 (A operand)
__device__ h16 g_KpHi[(long long)Bv*Hv*LKv*HDv];    // Kp [bh][lk][64] hi/lo
__device__ h16 g_KpLo[(long long)Bv*Hv*LKv*HDv];
__device__ h16 g_VtpHi[(long long)Bv*Hv*HDv*LKv];   // Vp^T [bh][d][256] hi/lo
__device__ h16 g_VtpLo[(long long)Bv*Hv*HDv*LKv];
__device__ float g_PP[(long long)PSPLIT*Bv*Hv*2*128*128];  // proj partials
__device__ float g_bias3[3 * Dv];               // packed [bq|bk|bv]

// ---------------- helpers ----------------------------------------------------
__device__ __forceinline__ void hsplit(float v, h16& h, h16& l) {
    h = __float2half_rn(v);
    l = __float2half_rn(v - __half2float(h));
}
__device__ __forceinline__ unsigned pack2(h16 a, h16 b) {
    __half2 t = __halves2half2(a, b);
    return *reinterpret_cast<unsigned*>(&t);
}

// D += A(16x16,row) * B(16x8,col)   (fp16 in, fp32 acc)
__device__ __forceinline__ void mma_f16(float* d, const unsigned* a,
                                        const unsigned* b) {
    asm volatile(
        "mma.sync.aligned.m16n8k16.row.col.f32.f16.f16.f32 "
        "{%0,%1,%2,%3}, {%4,%5,%6,%7}, {%8,%9}, {%0,%1,%2,%3};\n"
        : "+f"(d[0]), "+f"(d[1]), "+f"(d[2]), "+f"(d[3])
        : "r"(a[0]), "r"(a[1]), "r"(a[2]), "r"(a[3]),
          "r"(b[0]), "r"(b[1]));
}

__device__ __forceinline__ void ldsm4(unsigned& r0, unsigned& r1,
                                      unsigned& r2, unsigned& r3, unsigned addr) {
    asm volatile("ldmatrix.sync.aligned.m8n8.x4.shared.b16 {%0,%1,%2,%3}, [%4];\n"
                 : "=r"(r0), "=r"(r1), "=r"(r2), "=r"(r3) : "r"(addr));
}

__device__ __forceinline__ void cp16(unsigned dst, const void* src) {
    asm volatile("cp.async.cg.shared.global [%0], [%1], 16;\n" :: "r"(dst), "l"(src));
}
__device__ __forceinline__ void cp_commit() { asm volatile("cp.async.commit_group;\n"); }
__device__ __forceinline__ void cp_wait2()  { asm volatile("cp.async.wait_group 2;\n"); }
__device__ __forceinline__ void cp_wait0()  { asm volatile("cp.async.wait_group 0;\n"); }

// swizzle for 64B rows: chunk' = chunk ^ ((row>>1)&3), in 16B units
__device__ __forceinline__ unsigned swz16(int row, int chunk) {
    return (unsigned)(row * 4 + (chunk ^ ((row >> 1) & 3)));
}

// ============================================================================
// GEMM core (fp16x2): C[128x128] += Ahi[128,*] * (Bhi+Blo)[128,*]^T
// 2 MMAs per output (hi*hi + hi*lo). BK=32, FOUR-stage cp.async pipeline
// (prefetch distance 3), A-fragment double buffering (LDSM issued 8 MMAs
// ahead of first use). Warps 2x4, warp tile 64x32.
// ============================================================================
template<int BSPLIT>
__device__ __forceinline__ void gemm_core(
    const h16* __restrict__ Ahg,
    const h16* __restrict__ Bhg, const h16* __restrict__ Blg,
    const h16* __restrict__ Bh2, const h16* __restrict__ Bl2,
    int K, int ld,
    float (&acc)[4][4][4])
{
    constexpr int BK = 32;
    constexpr int A_ELE = 128*BK, B_ELE = 128*BK;
    constexpr unsigned OF_BH = A_ELE*2;
    constexpr unsigned OF_BL = (A_ELE+B_ELE)*2;
    constexpr unsigned STAGE_B = (A_ELE+2*B_ELE)*2;   // 24576

    extern __shared__ h16 smem_dyn[];
    const unsigned s0 = (unsigned)__cvta_generic_to_shared(smem_dyn);

    const int t = threadIdx.x, lane = t & 31, warp = t >> 5;
    const int wm = warp >> 2, wn = warp & 3;
    const int m_w = wm * 64, n_w = wn * 32;

    // ---- cp.async mappings ----
    const int a_row = t >> 1;
    const int a_c0  = (t & 1) * 2;
    const unsigned a_d0 = swz16(a_row, a_c0)     * 16;
    const unsigned a_d1 = swz16(a_row, a_c0 + 1) * 16;

    const int b_row = t >> 1;
    const int b_c0  = (t & 1) * 2;
    const unsigned b_d0 = swz16(b_row, b_c0)     * 16;
    const unsigned b_d1 = swz16(b_row, b_c0 + 1) * 16;

    const h16* browH;
    const h16* browL;
    if (BSPLIT > 0 && b_row >= BSPLIT) {
        browH = Bh2 + (size_t)(b_row - BSPLIT) * ld;
        browL = Bl2 + (size_t)(b_row - BSPLIT) * ld;
    } else {
        browH = Bhg + (size_t)b_row * ld;
        browL = Blg + (size_t)b_row * ld;
    }

    auto issue = [&](int st, int k0) {
        const unsigned sbs = s0 + (unsigned)st * STAGE_B;
        const char* pah = (const char*)(Ahg + (size_t)a_row * ld + k0);
        cp16(sbs + a_d0, pah + a_c0*16);
        cp16(sbs + a_d1, pah + a_c0*16 + 16);
        const char* pbh = (const char*)(browH + k0);
        const char* pbl = (const char*)(browL + k0);
        cp16(sbs + OF_BH + b_d0, pbh + b_c0*16);
        cp16(sbs + OF_BH + b_d1, pbh + b_c0*16 + 16);
        cp16(sbs + OF_BL + b_d0, pbl + b_c0*16);
        cp16(sbs + OF_BL + b_d1, pbl + b_c0*16 + 16);
    };

    // ---- ldmatrix fragment addresses ----
    const int lr  = lane & 7;
    const int aLR = lr + ((lane >> 3) & 1) * 8;
    const int aLC = lane >> 4;
    unsigned adA[4][2];
    #pragma unroll
    for (int mt = 0; mt < 4; mt++)
        #pragma unroll
        for (int ks = 0; ks < 2; ks++) {
            int row = m_w + mt*16 + aLR;
            adA[mt][ks] = swz16(row, 2*ks + aLC) * 16;
        }
    const int j   = lane >> 3;
    const int bLR = ((j >> 1) & 1) * 8 + lr;
    const int bLC = j & 1;
    unsigned adB[2][2];
    #pragma unroll
    for (int p = 0; p < 2; p++)
        #pragma unroll
        for (int ks = 0; ks < 2; ks++) {
            int row = n_w + p*16 + bLR;
            adB[p][ks] = swz16(row, 2*ks + bLC) * 16;
        }

    const int ntiles = K / BK;   // >= 8 at every call site
    issue(0, 0);        cp_commit();
    issue(1, BK);       cp_commit();
    issue(2, 2 * BK);   cp_commit();

    for (int i = 0; i < ntiles; i++) {
        cp_wait2();                         // group i complete (<=2 pending)
        __syncthreads();                    // stage (i+3)&3 free to refill
        if (i + 3 < ntiles) { issue((i + 3) & 3, (i + 3) * BK); cp_commit(); }

        const unsigned sbs = s0 + (unsigned)(i & 3) * STAGE_B;
        #pragma unroll
        for (int ks = 0; ks < 2; ks++) {
            unsigned bh[4][2], bl[4][2];
            #pragma unroll
            for (int p = 0; p < 2; p++) {
                ldsm4(bh[2*p][0], bh[2*p][1], bh[2*p+1][0], bh[2*p+1][1],
                      sbs + OF_BH + adB[p][ks]);
                ldsm4(bl[2*p][0], bl[2*p][1], bl[2*p+1][0], bl[2*p+1][1],
                      sbs + OF_BL + adB[p][ks]);
            }
            // A-fragment double buffer: LDSM for mt+1 issued before mt's MMAs
            unsigned ah0[4], ah1[4];
            ldsm4(ah0[0], ah0[1], ah0[2], ah0[3], sbs + adA[0][ks]);
            #pragma unroll
            for (int mt = 0; mt < 4; mt++) {
                unsigned* cur = (mt & 1) ? ah1 : ah0;
                unsigned* nxt = (mt & 1) ? ah0 : ah1;
                if (mt < 3)
                    ldsm4(nxt[0], nxt[1], nxt[2], nxt[3], sbs + adA[mt+1][ks]);
                #pragma unroll
                for (int nt = 0; nt < 4; nt++)
                    mma_f16(acc[mt][nt], cur, bh[nt]);
                #pragma unroll
                for (int nt = 0; nt < 4; nt++)
                    mma_f16(acc[mt][nt], cur, bl[nt]);
            }
        }
    }
}

// ============================================================================
// Fused QKV GEMM (CTA 128x128). grid = (24, 128).
// ============================================================================
__global__ __launch_bounds__(256, 2) void gemm_qkv(
    const h16* __restrict__ Ahi,
    const h16* __restrict__ Bhi, const h16* __restrict__ Blo,
    const float* __restrict__ mask)
{
    extern __shared__ h16 smem_dyn[];
    const int m0 = blockIdx.y * 128, n0 = blockIdx.x * 128;
    float acc[4][4][4];
    #pragma unroll
    for (int a = 0; a < 4; a++)
        #pragma unroll
        for (int b = 0; b < 4; b++)
            #pragma unroll
            for (int c = 0; c < 4; c++) acc[a][b][c] = 0.0f;

    gemm_core<0>(Ahi + (size_t)m0 * Dv,
                 Bhi + (size_t)n0 * Dv, Blo + (size_t)n0 * Dv,
                 nullptr, nullptr, Dv, Dv, acc);

    const int t = threadIdx.x;
    const int lane = t & 31, warp = t >> 5;
    const int wm = warp >> 2, wn = warp & 3;
    const int gid = lane >> 2, tig = lane & 3;

    const bool isQ = (n0 < Dv);
    const bool isV = (n0 >= 2 * Dv);
    const int dbase = isQ ? 0 : (isV ? 2 * Dv : Dv);

    if (isQ) {
        #pragma unroll
        for (int mt = 0; mt < 4; mt++) {
            const int r0 = m0 + wm * 64 + mt * 16 + gid;
            #pragma unroll
            for (int nt = 0; nt < 4; nt++) {
                const int c = n0 + wn * 32 + nt * 8 + tig * 2;
                const float b0 = g_bias3[c], b1 = g_bias3[c + 1];
                *(unsigned*)&g_QHi[(size_t)r0 * Dv + c] =
                    pack2(__float2half_rn(acc[mt][nt][0] + b0),
                          __float2half_rn(acc[mt][nt][1] + b1));
                *(unsigned*)&g_QHi[(size_t)(r0+8) * Dv + c] =
                    pack2(__float2half_rn(acc[mt][nt][2] + b0),
                          __float2half_rn(acc[mt][nt][3] + b1));
            }
        }
    } else {
        h16* oh = isV ? g_Vt_hi : g_Kt_hi;
        h16* ol = isV ? g_Vt_lo : g_Kt_lo;
        float* Ts = (float*)smem_dyn;
        __syncthreads();
        #pragma unroll
        for (int mt = 0; mt < 4; mt++) {
            const int ml = wm * 64 + mt * 16 + gid;
            const int r0 = m0 + ml;
            const float ms0 = mask[r0], ms1 = mask[r0 + 8];
            #pragma unroll
            for (int nt = 0; nt < 4; nt++) {
                const int nl = wn * 32 + nt * 8 + tig * 2;
                const int c  = n0 + nl;
                const float b0 = g_bias3[c], b1 = g_bias3[c + 1];
                Ts[nl*132 + ml]         = (acc[mt][nt][0] + b0) * ms0;
                Ts[(nl+1)*132 + ml]     = (acc[mt][nt][1] + b1) * ms0;
                Ts[nl*132 + ml + 8]     = (acc[mt][nt][2] + b0) * ms1;
                Ts[(nl+1)*132 + ml + 8] = (acc[mt][nt][3] + b1) * ms1;
            }
        }
        __syncthreads();
        const int nl = t >> 1, mc = (t & 1) * 64;
        const int d  = n0 - dbase + nl;
        const size_t ad = ((size_t)(m0 >> 12) << 22) + (size_t)d * 4096
                        + (m0 & 4095) + mc;
        unsigned hb[32], lb[32];
        #pragma unroll
        for (int i = 0; i < 32; i++) {
            float2 v = *(float2*)&Ts[nl*132 + mc + 2*i];
            h16 h0,l0,h1,l1; hsplit(v.x,h0,l0); hsplit(v.y,h1,l1);
            hb[i] = pack2(h0,h1); lb[i] = pack2(l0,l1);
        }
        #pragma unroll
        for (int i = 0; i < 8; i++) {
            *(uint4*)&oh[ad + i*8] = ((uint4*)hb)[i];
            *(uint4*)&ol[ad + i*8] = ((uint4*)lb)[i];
        }
    }
}

// ============================================================================
// Output GEMM: out = Xo @ Wo + bo (fp32). grid = (8, 128).
// ============================================================================
__global__ __launch_bounds__(256, 2) void gemm_out(
    const h16* __restrict__ Ahi,
    const h16* __restrict__ Bhi, const h16* __restrict__ Blo,
    const float* __restrict__ bias, float* __restrict__ outf)
{
    const int m0 = blockIdx.y * 128, n0 = blockIdx.x * 128;
    float acc[4][4][4];
    #pragma unroll
    for (int a = 0; a < 4; a++)
        #pragma unroll
        for (int b = 0; b < 4; b++)
            #pragma unroll
            for (int c = 0; c < 4; c++) acc[a][b][c] = 0.0f;

    gemm_core<0>(Ahi + (size_t)m0 * Dv,
                 Bhi + (size_t)n0 * Dv, Blo + (size_t)n0 * Dv,
                 nullptr, nullptr, Dv, Dv, acc);

    const int lane = threadIdx.x & 31, warp = threadIdx.x >> 5;
    const int wm = warp >> 2, wn = warp & 3;
    const int gid = lane >> 2, tig = lane & 3;

    #pragma unroll
    for (int mt = 0; mt < 4; mt++) {
        const int r0 = m0 + wm * 64 + mt * 16 + gid;
        #pragma unroll
        for (int nt = 0; nt < 4; nt++) {
            const int c = n0 + wn * 32 + nt * 8 + tig * 2;
            const float b0 = bias[c], b1 = bias[c + 1];
            *(float2*)&outf[(size_t)r0       * Dv + c] =
                make_float2(acc[mt][nt][0] + b0, acc[mt][nt][1] + b1);
            *(float2*)&outf[(size_t)(r0 + 8) * Dv + c] =
                make_float2(acc[mt][nt][2] + b0, acc[mt][nt][3] + b1);
        }
    }
}

// ============================================================================
// Projection split-K stage 1: partial over s-slice. grid = (2, 64, PSPLIT).
// ============================================================================
__global__ __launch_bounds__(256, 2) void proj_part()
{
    const int m0 = blockIdx.x * 128;
    const int bh = blockIdx.y;
    const int z  = blockIdx.z;
    const int b  = bh >> 4, h = bh & 15;
    const int soff = z * (Sv / PSPLIT);

    const h16* Ah = g_Ehi + ((size_t)h * LKv + m0) * Sv + soff;
    const size_t boff = (size_t)(b * Dv + h * HDv) * Sv + soff;

    float acc[4][4][4];
    #pragma unroll
    for (int a = 0; a < 4; a++)
        #pragma unroll
        for (int c = 0; c < 4; c++)
            #pragma unroll
            for (int r = 0; r < 4; r++) acc[a][c][r] = 0.0f;

    gemm_core<64>(Ah,
                  g_Kt_hi + boff, g_Kt_lo + boff,
                  g_Vt_hi + boff, g_Vt_lo + boff,
                  Sv / PSPLIT, Sv, acc);

    const int lane = threadIdx.x & 31, warp = threadIdx.x >> 5;
    const int wm = warp >> 2, wn = warp & 3;
    const int gid = lane >> 2, tig = lane & 3;

    float* pp = g_PP + (((size_t)z * (Bv*Hv) + bh) * 2 + blockIdx.x) * 128 * 128;
    #pragma unroll
    for (int mt = 0; mt < 4; mt++) {
        const int ml = wm * 64 + mt * 16 + gid;
        #pragma unroll
        for (int nt = 0; nt < 4; nt++) {
            const int nl = wn * 32 + nt * 8 + tig * 2;
            *(float2*)&pp[(size_t)ml * 128 + nl]       =
                make_float2(acc[mt][nt][0], acc[mt][nt][1]);
            *(float2*)&pp[(size_t)(ml + 8) * 128 + nl] =
                make_float2(acc[mt][nt][2], acc[mt][nt][3]);
        }
    }
}

// ============================================================================
// Projection split-K stage 2: sum partials, split-store Kp + VpT (coalesced).
// grid = (2, 64), 256 threads, smem Ts[128][132] fp32.
// ============================================================================
__global__ __launch_bounds__(256) void proj_reduce()
{
    extern __shared__ h16 smem_dyn[];
    float* Ts = (float*)smem_dyn;
    const int m0 = blockIdx.x * 128;
    const int bh = blockIdx.y;
    const int t  = threadIdx.x;

    const float* pp = g_PP + ((size_t)bh * 2 + blockIdx.x) * 128 * 128;
    const size_t zstride = (size_t)(Bv*Hv) * 2 * 128 * 128;

    #pragma unroll
    for (int i = 0; i < 16; i++) {
        int idx = t + i * 256;
        int ml = idx >> 5, nc = idx & 31;
        float4 s = *(const float4*)&pp[(size_t)ml * 128 + nc * 4];
        #pragma unroll
        for (int z = 1; z < PSPLIT; z++) {
            float4 v = *(const float4*)&pp[z * zstride + (size_t)ml * 128 + nc * 4];
            s.x += v.x; s.y += v.y; s.z += v.z; s.w += v.w;
        }
        *(float4*)&Ts[ml * 132 + nc * 4] = s;
    }
    __syncthreads();

    h16* kpH = g_KpHi + (size_t)bh * LKv * HDv;
    h16* kpL = g_KpLo + (size_t)bh * LKv * HDv;
    h16* vtH = g_VtpHi + (size_t)bh * HDv * LKv;
    h16* vtL = g_VtpLo + (size_t)bh * HDv * LKv;

    // Kp: [lk][64] coalesced
    {
        const int lk = t >> 1, c0 = (t & 1) * 32;
        unsigned hb[16], lb[16];
        #pragma unroll
        for (int i = 0; i < 16; i++) {
            float2 v = *(float2*)&Ts[lk*132 + c0 + 2*i];
            h16 h0,l0,h1,l1; hsplit(v.x,h0,l0); hsplit(v.y,h1,l1);
            hb[i] = pack2(h0,h1); lb[i] = pack2(l0,l1);
        }
        const size_t base = (size_t)(m0 + lk) * HDv + c0;
        #pragma unroll
        for (int i = 0; i < 4; i++) {
            *(uint4*)&kpH[base + i*8] = ((uint4*)hb)[i];
            *(uint4*)&kpL[base + i*8] = ((uint4*)lb)[i];
        }
    }
    // VpT: [d][256] coalesced
    {
        const int d = t >> 2, kc = (t & 3) * 32;
        unsigned hb[16], lb[16];
        #pragma unroll
        for (int i = 0; i < 16; i++) {
            float va = Ts[(kc + 2*i)*132 + 64 + d];
            float vb = Ts[(kc + 2*i + 1)*132 + 64 + d];
            h16 h0,l0,h1,l1; hsplit(va,h0,l0); hsplit(vb,h1,l1);
            hb[i] = pack2(h0,h1); lb[i] = pack2(l0,l1);
        }
        const size_t base = (size_t)d * LKv + m0 + kc;
        #pragma unroll
        for (int i = 0; i < 4; i++) {
            *(uint4*)&vtH[base + i*8] = ((uint4*)hb)[i];
            *(uint4*)&vtL[base + i*8] = ((uint4*)lb)[i];
        }
    }
}

// ============================================================================
// Prepass kernels
// ============================================================================
#define NB_SPLIT ((int)(NELEM/4/256))   // 16384

__global__ void prepass_split(const float* __restrict__ X, const float* __restrict__ E,
                              const float* __restrict__ bq, const float* __restrict__ bk,
                              const float* __restrict__ bv)
{
    const int bid = blockIdx.x;
    if (bid < 2 * NB_SPLIT) {
        const bool isX = bid < NB_SPLIT;
        const float* in = isX ? X : E;
        h16* hi = isX ? g_Xhi : g_Ehi;
        const int base = (isX ? bid : bid - NB_SPLIT);
        long long i = ((long long)base * 256 + threadIdx.x);
        float4 v = *(const float4*)&in[i * 4];
        uint2 o;
        o.x = pack2(__float2half_rn(v.x), __float2half_rn(v.y));
        o.y = pack2(__float2half_rn(v.z), __float2half_rn(v.w));
        *(uint2*)&hi[i * 4] = o;
    } else {
        for (int i = threadIdx.x; i < 3 * Dv; i += 256) {
            g_bias3[i] = (i < Dv) ? bq[i]
                       : (i < 2 * Dv) ? bk[i - Dv] : bv[i - 2 * Dv];
        }
    }
}

__global__ void prepass_tsplit(const float* __restrict__ Wq, const float* __restrict__ Wk,
                               const float* __restrict__ Wv, const float* __restrict__ Wo)
{
    __shared__ float ts[32][33];
    const float* in = (blockIdx.z == 0) ? Wq : (blockIdx.z == 1) ? Wk
                    : (blockIdx.z == 2) ? Wv : Wo;
    h16* hi = g_Wt_hi[blockIdx.z];
    h16* lo = g_Wt_lo[blockIdx.z];
    const int bx = blockIdx.x * 32, by = blockIdx.y * 32;
    const int tx = threadIdx.x, ty = threadIdx.y;
    #pragma unroll
    for (int j = 0; j < 4; j++)
        ts[ty + j * 8][tx] = in[(size_t)(by + ty + j * 8) * Dv + bx + tx];
    __syncthreads();
    #pragma unroll
    for (int j = 0; j < 4; j++) {
        float v = ts[tx][ty + j * 8];
        h16 h, l; hsplit(v, h, l);
        size_t ad = (size_t)(bx + ty + j * 8) * Dv + by + tx;
        hi[ad] = h; lo[ad] = l;
    }
}

// ============================================================================
// Tensorized attention, online softmax, fp16x2 (unchanged).
// smem: QH 0 (16K) | KH 16K | KL 32K | VH 48K | VL 64K  (80KB)
// ============================================================================
#define ATTN_SMEM 81920

__global__ __launch_bounds__(256) void attn_mma()
{
    extern __shared__ char smraw[];
    const unsigned sb = (unsigned)__cvta_generic_to_shared(smraw);

    const int t = threadIdx.x, lane = t & 31, warp = t >> 5;
    const int bh = blockIdx.y, b = bh >> 4, h = bh & 15;
    const int q0 = blockIdx.x * 128;

    const h16* QgH = g_QHi + (size_t)(b * Sv + q0) * Dv + h * HDv;
    const h16* KpH = g_KpHi + (size_t)bh * LKv * HDv;
    const h16* KpL = g_KpLo + (size_t)bh * LKv * HDv;
    const h16* VtH = g_VtpHi + (size_t)bh * HDv * LKv;
    const h16* VtL = g_VtpLo + (size_t)bh * HDv * LKv;

    const unsigned QH = 0, KH = 16384, KL = 32768, VH = 49152, VL = 65536;

    const int qrow = t >> 1, qc0 = (t & 1) * 4;
    const int vrow = t >> 2, vc0 = (t & 3) * 4;

    #pragma unroll
    for (int c4 = 0; c4 < 4; c4++) {
        int ch = qc0 + c4;
        unsigned off = (unsigned)qrow * 128 + (unsigned)(ch ^ (qrow & 7)) * 16;
        cp16(sb + QH + off, QgH + (size_t)qrow * Dv + ch * 8);
    }

    auto stageKV = [&](int c) {
        #pragma unroll
        for (int c4 = 0; c4 < 4; c4++) {
            int ch = qc0 + c4;
            unsigned off = (unsigned)qrow * 128 + (unsigned)(ch ^ (qrow & 7)) * 16;
            cp16(sb + KH + off, KpH + (size_t)(c * 128 + qrow) * HDv + ch * 8);
            cp16(sb + KL + off, KpL + (size_t)(c * 128 + qrow) * HDv + ch * 8);
        }
        #pragma unroll
        for (int c4 = 0; c4 < 4; c4++) {
            int ch = vc0 + c4;
            unsigned off = (unsigned)vrow * 256 + (unsigned)(ch ^ (vrow & 7)) * 16;
            cp16(sb + VH + off, VtH + (size_t)vrow * LKv + c * 128 + ch * 8);
            cp16(sb + VL + off, VtL + (size_t)vrow * LKv + c * 128 + ch * 8);
        }
    };

    stageKV(0);
    cp_commit();

    const int gid = lane >> 2, tig = lane & 3;
    const int lr  = lane & 7;
    const int aLR = lr + ((lane >> 3) & 1) * 8;
    const int aLC = lane >> 4;
    const int jj  = lane >> 3;
    const int bLR = ((jj >> 1) & 1) * 8 + lr;
    const int bLC = jj & 1;
    const int m_w = warp * 16;
    const int rowA = m_w + aLR;

    float avacc[8][4];
    #pragma unroll
    for (int nt = 0; nt < 8; nt++)
        #pragma unroll
        for (int r = 0; r < 4; r++) avacc[nt][r] = 0.0f;
    float m0r = -1e30f, m1r = -1e30f, sum0 = 0.0f, sum1 = 0.0f;

    for (int c = 0; c < 2; c++) {
        cp_wait0();
        __syncthreads();

        float sacc[16][4];
        #pragma unroll
        for (int nt = 0; nt < 16; nt++)
            #pragma unroll
            for (int r = 0; r < 4; r++) sacc[nt][r] = 0.0f;

        #pragma unroll
        for (int ks = 0; ks < 4; ks++) {
            unsigned qh[4];
            unsigned aoff = (unsigned)rowA * 128 + ((unsigned)((2*ks + aLC) ^ (rowA & 7))) * 16;
            ldsm4(qh[0], qh[1], qh[2], qh[3], sb + QH + aoff);
            #pragma unroll
            for (int p = 0; p < 8; p += 2) {
                int rB0 = p * 16 + bLR, rB1 = (p + 1) * 16 + bLR;
                unsigned bo0 = (unsigned)rB0 * 128 + ((unsigned)((2*ks + bLC) ^ (rB0 & 7))) * 16;
                unsigned bo1 = (unsigned)rB1 * 128 + ((unsigned)((2*ks + bLC) ^ (rB1 & 7))) * 16;
                unsigned kh0[4], kl0[4], kh1[4], kl1[4];
                ldsm4(kh0[0], kh0[1], kh0[2], kh0[3], sb + KH + bo0);
                ldsm4(kl0[0], kl0[1], kl0[2], kl0[3], sb + KL + bo0);
                ldsm4(kh1[0], kh1[1], kh1[2], kh1[3], sb + KH + bo1);
                ldsm4(kl1[0], kl1[1], kl1[2], kl1[3], sb + KL + bo1);
                mma_f16(sacc[2*p],   qh, &kh0[0]);
                mma_f16(sacc[2*p+1], qh, &kh0[2]);
                mma_f16(sacc[2*p+2], qh, &kh1[0]);
                mma_f16(sacc[2*p+3], qh, &kh1[2]);
                mma_f16(sacc[2*p],   qh, &kl0[0]);
                mma_f16(sacc[2*p+1], qh, &kl0[2]);
                mma_f16(sacc[2*p+2], qh, &kl1[0]);
                mma_f16(sacc[2*p+3], qh, &kl1[2]);
            }
        }

        float mc0 = -1e30f, mc1 = -1e30f;
        #pragma unroll
        for (int nt = 0; nt < 16; nt++) {
            mc0 = fmaxf(mc0, fmaxf(sacc[nt][0], sacc[nt][1]));
            mc1 = fmaxf(mc1, fmaxf(sacc[nt][2], sacc[nt][3]));
        }
        mc0 *= 0.125f; mc1 *= 0.125f;
        mc0 = fmaxf(mc0, __shfl_xor_sync(0xffffffffu, mc0, 1));
        mc0 = fmaxf(mc0, __shfl_xor_sync(0xffffffffu, mc0, 2));
        mc1 = fmaxf(mc1, __shfl_xor_sync(0xffffffffu, mc1, 1));
        mc1 = fmaxf(mc1, __shfl_xor_sync(0xffffffffu, mc1, 2));
        const float mn0 = fmaxf(m0r, mc0), mn1 = fmaxf(m1r, mc1);
        const float sc0 = __expf(m0r - mn0), sc1 = __expf(m1r - mn1);
        m0r = mn0; m1r = mn1;

        float rs0 = 0.0f, rs1 = 0.0f;
        #pragma unroll
        for (int nt = 0; nt < 16; nt++) {
            float p0 = __expf(0.125f * sacc[nt][0] - mn0);
            float p1 = __expf(0.125f * sacc[nt][1] - mn0);
            float p2 = __expf(0.125f * sacc[nt][2] - mn1);
            float p3 = __expf(0.125f * sacc[nt][3] - mn1);
            sacc[nt][0] = p0; sacc[nt][1] = p1; sacc[nt][2] = p2; sacc[nt][3] = p3;
            rs0 += p0 + p1; rs1 += p2 + p3;
        }
        rs0 += __shfl_xor_sync(0xffffffffu, rs0, 1);
        rs0 += __shfl_xor_sync(0xffffffffu, rs0, 2);
        rs1 += __shfl_xor_sync(0xffffffffu, rs1, 1);
        rs1 += __shfl_xor_sync(0xffffffffu, rs1, 2);
        sum0 = sum0 * sc0 + rs0;
        sum1 = sum1 * sc1 + rs1;
        #pragma unroll
        for (int nt = 0; nt < 8; nt++) {
            avacc[nt][0] *= sc0; avacc[nt][1] *= sc0;
            avacc[nt][2] *= sc1; avacc[nt][3] *= sc1;
        }

        #pragma unroll
        for (int kt = 0; kt < 8; kt++) {
            unsigned ah[4] = {
                pack2(__float2half_rn(sacc[2*kt][0]),   __float2half_rn(sacc[2*kt][1])),
                pack2(__float2half_rn(sacc[2*kt][2]),   __float2half_rn(sacc[2*kt][3])),
                pack2(__float2half_rn(sacc[2*kt+1][0]), __float2half_rn(sacc[2*kt+1][1])),
                pack2(__float2half_rn(sacc[2*kt+1][2]), __float2half_rn(sacc[2*kt+1][3]))
            };
            #pragma unroll
            for (int p = 0; p < 4; p += 2) {
                int rB0 = p * 16 + bLR, rB1 = (p + 1) * 16 + bLR;
                unsigned bo0 = (unsigned)rB0 * 256 + ((unsigned)((2*kt + bLC) ^ (rB0 & 7))) * 16;
                unsigned bo1 = (unsigned)rB1 * 256 + ((unsigned)((2*kt + bLC) ^ (rB1 & 7))) * 16;
                unsigned vh0[4], vl0[4], vh1[4], vl1[4];
                ldsm4(vh0[0], vh0[1], vh0[2], vh0[3], sb + VH + bo0);
                ldsm4(vl0[0], vl0[1], vl0[2], vl0[3], sb + VL + bo0);
                ldsm4(vh1[0], vh1[1], vh1[2], vh1[3], sb + VH + bo1);
                ldsm4(vl1[0], vl1[1], vl1[2], vl1[3], sb + VL + bo1);
                mma_f16(avacc[2*p],   ah, &vh0[0]);
                mma_f16(avacc[2*p+1], ah, &vh0[2]);
                mma_f16(avacc[2*p+2], ah, &vh1[0]);
                mma_f16(avacc[2*p+3], ah, &vh1[2]);
                mma_f16(avacc[2*p],   ah, &vl0[0]);
                mma_f16(avacc[2*p+1], ah, &vl0[2]);
                mma_f16(avacc[2*p+2], ah, &vl1[0]);
                mma_f16(avacc[2*p+3], ah, &vl1[2]);
            }
        }
        __syncthreads();
        if (c == 0) { stageKV(1); cp_commit(); }
    }

    const float i0 = 1.0f / sum0, i1 = 1.0f / sum1;
    float* Xs = (float*)(smraw + 16384);
    #pragma unroll
    for (int nt = 0; nt < 8; nt++) {
        const int col = 8 * nt + 2 * tig;
        Xs[(m_w + gid)     * 64 + col]     = avacc[nt][0] * i0;
        Xs[(m_w + gid)     * 64 + col + 1] = avacc[nt][1] * i0;
        Xs[(m_w + gid + 8) * 64 + col]     = avacc[nt][2] * i1;
        Xs[(m_w + gid + 8) * 64 + col + 1] = avacc[nt][3] * i1;
    }
    __syncthreads();

    #pragma unroll
    for (int r = 0; r < 8; r++) {
        int i = (t + r * 256) * 4;
        int row = i >> 6, d0 = i & 63;
        float4 v = *(const float4*)&Xs[row * 64 + d0];
        size_t ad = ((size_t)(b * Sv + q0 + row)) * Dv + h * HDv + d0;
        uint2 o;
        o.x = pack2(__float2half_rn(v.x), __float2half_rn(v.y));
        o.y = pack2(__float2half_rn(v.z), __float2half_rn(v.w));
        *(uint2*)&g_XoHi[ad] = o;
    }
}

// ============================================================================
extern "C" void kernel_launch(void* const* d_in, const int* in_sizes, int n_in,
                              void* d_out, int out_size)
{
    const float* X    = (const float*)d_in[0];
    const float* mask = (const float*)d_in[1];
    const float* Wq   = (const float*)d_in[2];
    const float* bq   = (const float*)d_in[3];
    const float* Wk   = (const float*)d_in[4];
    const float* bk   = (const float*)d_in[5];
    const float* Wv   = (const float*)d_in[6];
    const float* bv   = (const float*)d_in[7];
    const float* E    = (const float*)d_in[8];
    const float* Wo   = (const float*)d_in[9];
    const float* bo   = (const float*)d_in[10];
    float* out        = (float*)d_out;

    h16 *xhi, *wth, *wtl, *xoh;
    cudaGetSymbolAddress((void**)&xhi, g_Xhi);
    cudaGetSymbolAddress((void**)&wth, g_Wt_hi);
    cudaGetSymbolAddress((void**)&wtl, g_Wt_lo);
    cudaGetSymbolAddress((void**)&xoh, g_XoHi);

    const long long WSZ = (long long)Dv * Dv;

    const int SMEM_G = 4 * 24576;       // fp16x2 core: 4 stages x 24KB = 96KB
    const int SMEM_R = 128 * 132 * 4;   // reduce staging
    cudaFuncSetAttribute(gemm_qkv,   cudaFuncAttributeMaxDynamicSharedMemorySize, SMEM_G);
    cudaFuncSetAttribute(gemm_out,   cudaFuncAttributeMaxDynamicSharedMemorySize, SMEM_G);
    cudaFuncSetAttribute(proj_part,  cudaFuncAttributeMaxDynamicSharedMemorySize, SMEM_G);
    cudaFuncSetAttribute(proj_reduce,cudaFuncAttributeMaxDynamicSharedMemorySize, SMEM_R);
    cudaFuncSetAttribute(attn_mma,   cudaFuncAttributeMaxDynamicSharedMemorySize, ATTN_SMEM);

    // launch 1: convert X + E to fp16, pack bias
    prepass_split<<<2 * NB_SPLIT + 1, 256>>>(X, E, bq, bk, bv);
    // launch 2: transpose+split all weights (fp16 hi/lo)
    prepass_tsplit<<<dim3(32, 32, 4), dim3(32, 8)>>>(Wq, Wk, Wv, Wo);
    // launch 3: fused QKV
    gemm_qkv<<<dim3(3 * Dv / 128, Mrows / 128), 256, SMEM_G>>>(xhi, wth, wtl, mask);
    // launch 4: proj partials (split-K)
    proj_part<<<dim3(LKv / 128, Bv * Hv, PSPLIT), 256, SMEM_G>>>();
    // launch 5: proj reduce + split stores
    proj_reduce<<<dim3(LKv / 128, Bv * Hv), 256, SMEM_R>>>();
    // launch 6: attention
    attn_mma<<<dim3(Sv / 128, Bv * Hv), 256, ATTN_SMEM>>>();
    // launch 7: output projection
    gemm_out<<<dim3(Dv / 128, Mrows / 128), 256, SMEM_G>>>(xoh, wth + 3*WSZ, wtl + 3*WSZ,
                                                           bo, out);
}